// round 1
// baseline (speedup 1.0000x reference)
#include <cuda_runtime.h>
#include <math.h>

// Problem constants
#define NB   8      // batch
#define CC_  192    // channels
#define HH   112
#define WW   112
#define TILE 16
#define HALO 18                 // TILE + 2
#define POS  (HALO * HALO)      // 324
#define CCH  32                 // channels per chunk
#define NCHUNK (CC_ / CCH)      // 6
#define INV_T 10.0f             // 1 / 0.1
#define TOTAL_TERMS (8.0 * 8.0 * 112.0 * 112.0)  // N*M*H*W = 802816

__device__ double g_acc;

__global__ void dcl_zero_kernel() { g_acc = 0.0; }

__global__ __launch_bounds__(256)
void dcl_main_kernel(const float* __restrict__ feat,
                     const int*   __restrict__ labels,
                     const int*   __restrict__ dirs)
{
    __shared__ float s[CCH * POS];   // channel-major tile chunk: [c][pos]
    __shared__ float ssq[POS];       // per-position raw sum of squares (over all C)
    __shared__ float warpsum[8];

    const int n  = blockIdx.z;
    const int ti = blockIdx.y * TILE;
    const int tj = blockIdx.x * TILE;
    const int tid = threadIdx.x;
    const int li = tid >> 4;         // 0..15
    const int lj = tid & 15;         // 0..15
    const int gi = ti + li;
    const int gj = tj + lj;
    const int p0 = (li + 1) * HALO + (lj + 1);

    float dots[8];
#pragma unroll
    for (int k = 0; k < 8; k++) dots[k] = 0.0f;

    // init sumsq accumulators
    for (int p = tid; p < POS; p += 256) ssq[p] = 0.0f;

    for (int ch = 0; ch < NCHUNK; ch++) {
        const int c0 = ch * CCH;
        __syncthreads();  // readers of s from previous chunk done / ssq init done

        // ---- load chunk (zero-fill OOB halo; OOB values are never selected) ----
        for (int idx = tid; idx < CCH * POS; idx += 256) {
            const int c   = idx / POS;
            const int p   = idx - c * POS;
            const int r   = p / HALO;
            const int col = p - r * HALO;
            const int ii  = ti - 1 + r;
            const int jj  = tj - 1 + col;
            float v = 0.0f;
            if (ii >= 0 && ii < HH && jj >= 0 && jj < WW)
                v = feat[(((size_t)n * CC_ + c0 + c) * HH + ii) * WW + jj];
            s[idx] = v;
        }
        __syncthreads();

        // ---- per-position sum of squares (all 18x18 positions incl. halo) ----
        for (int p = tid; p < POS; p += 256) {
            float ss = 0.0f;
#pragma unroll
            for (int c = 0; c < CCH; c++) {
                float v = s[c * POS + p];
                ss = fmaf(v, v, ss);
            }
            ssq[p] += ss;
        }

        // ---- 8 neighbor raw dot products for this thread's center pixel ----
#pragma unroll
        for (int c = 0; c < CCH; c++) {
            const float* sc = s + c * POS;
            const float x = sc[p0];
            dots[0] = fmaf(x, sc[p0 - HALO - 1], dots[0]);
            dots[1] = fmaf(x, sc[p0 - HALO    ], dots[1]);
            dots[2] = fmaf(x, sc[p0 - HALO + 1], dots[2]);
            dots[3] = fmaf(x, sc[p0        - 1], dots[3]);
            dots[4] = fmaf(x, sc[p0        + 1], dots[4]);
            dots[5] = fmaf(x, sc[p0 + HALO - 1], dots[5]);
            dots[6] = fmaf(x, sc[p0 + HALO    ], dots[6]);
            dots[7] = fmaf(x, sc[p0 + HALO + 1], dots[7]);
        }
    }
    __syncthreads();  // ssq fully accumulated before neighbor reads

    // ---- per-pixel loss over the 8 "m" direction fields ----
    const float ssc  = ssq[p0];
    // 1/max(norm,1e-12) == rsqrt(ss) for ss >= 1e-24, else 1e12
    const float invp = (ssc >= 1e-24f) ? rsqrtf(ssc) : 1e12f;

    float logits[8];
    int   maskv[8];
    float esum = 0.0f;

#pragma unroll
    for (int m = 0; m < 8; m++) {
        const int d0 = dirs[(((size_t)m * 2 + 0) * HH + gi) * WW + gj];
        const int d1 = dirs[(((size_t)m * 2 + 1) * HH + gi) * WW + gj];
        const int k  = (d0 + 1) * 3 + (d1 + 1);   // 0..8

        float draw;
        if (k == 4)       draw = ssc;              // self: raw dot == sumsq
        else if (k < 4)   draw = dots[k];
        else              draw = dots[k - 1];

        float invq;
        if (k == 4) {
            invq = invp;
        } else {
            const float ssn = ssq[p0 + d0 * HALO + d1];
            invq = (ssn >= 1e-24f) ? rsqrtf(ssn) : 1e12f;
        }

        const float logit = draw * invp * invq * INV_T;

        const int labm = labels[((size_t)m * HH + gi) * WW + gj];
        const int labg = labels[((size_t)n * HH + (gi + d0)) * WW + (gj + d1)];
        const int mk   = (labm == labg);

        logits[m] = logit;
        maskv[m]  = mk;
        esum += mk ? expf(logit) : 0.0f;
    }

    const float ld = logf(esum + 1e-6f);
    float pix = 0.0f;
#pragma unroll
    for (int m = 0; m < 8; m++) {
        // mask==0 would give -log(0) = +inf in the reference; labels are all
        // zero for this problem so this branch never fires, but stay faithful.
        pix += maskv[m] ? (ld - logits[m]) : INFINITY;
    }

    // ---- block reduction (float warp shuffle -> double block partial) ----
    float v = pix;
#pragma unroll
    for (int off = 16; off > 0; off >>= 1)
        v += __shfl_xor_sync(0xffffffffu, v, off);
    if ((tid & 31) == 0) warpsum[tid >> 5] = v;
    __syncthreads();
    if (tid == 0) {
        double bs = 0.0;
#pragma unroll
        for (int w = 0; w < 8; w++) bs += (double)warpsum[w];
        atomicAdd(&g_acc, bs);
    }
}

__global__ void dcl_finalize_kernel(float* out) {
    out[0] = (float)(g_acc / TOTAL_TERMS);
}

extern "C" void kernel_launch(void* const* d_in, const int* in_sizes, int n_in,
                              void* d_out, int out_size)
{
    const float* feat   = (const float*)d_in[0];
    const int*   labels = (const int*)  d_in[1];
    const int*   dirs   = (const int*)  d_in[2];
    float*       out    = (float*)d_out;

    dcl_zero_kernel<<<1, 1>>>();
    dim3 grid(WW / TILE, HH / TILE, NB);   // (7, 7, 8)
    dcl_main_kernel<<<grid, 256>>>(feat, labels, dirs);
    dcl_finalize_kernel<<<1, 1>>>(out);
}